// round 4
// baseline (speedup 1.0000x reference)
#include <cuda_runtime.h>
#include <cuda_bf16.h>
#include <math.h>

#define Bn 4
#define Qn 1024
#define Dn 256
#define GH 64

// scratch for qW = q @ W  : [B*Q, D] = 4096 x 256 floats = 4MB
__device__ float g_qW[Bn * Qn * Dn];

// ---------------------------------------------------------------------------
// Kernel A: qW = q @ W.  M=4096, K=256, N=256. 64x64 tile, BK=16, 256 thr.
// ---------------------------------------------------------------------------
__global__ __launch_bounds__(256) void qw_gemm_kernel(
    const float* __restrict__ A,   // [4096, 256]
    const float* __restrict__ Wm,  // [256, 256]
    float* __restrict__ C)         // [4096, 256]
{
    __shared__ float As[16][65];   // [k][m], padded
    __shared__ float Bs[16][68];   // [k][n], padded

    const int tid = threadIdx.x;
    const int bm = blockIdx.x * 64;
    const int bn = blockIdx.y * 64;
    const int tr = tid >> 4;        // 0..15
    const int tc = tid & 15;        // 0..15

    float acc[4][4];
#pragma unroll
    for (int i = 0; i < 4; i++)
#pragma unroll
        for (int j = 0; j < 4; j++) acc[i][j] = 0.f;

    for (int k0 = 0; k0 < Dn; k0 += 16) {
        {
            int m = tid >> 2;
            int kk = (tid & 3) * 4;
            float4 v = *(const float4*)&A[(bm + m) * Dn + k0 + kk];
            As[kk + 0][m] = v.x; As[kk + 1][m] = v.y;
            As[kk + 2][m] = v.z; As[kk + 3][m] = v.w;
        }
        {
            int kk = tid >> 4;
            int n = (tid & 15) * 4;
            *(float4*)&Bs[kk][n] = *(const float4*)&Wm[(k0 + kk) * Dn + bn + n];
        }
        __syncthreads();
#pragma unroll
        for (int kk = 0; kk < 16; kk++) {
            float a[4];
            float4 b4 = *(const float4*)&Bs[kk][tc * 4];
            float b[4] = { b4.x, b4.y, b4.z, b4.w };
#pragma unroll
            for (int i = 0; i < 4; i++) a[i] = As[kk][tr * 4 + i];
#pragma unroll
            for (int i = 0; i < 4; i++)
#pragma unroll
                for (int j = 0; j < 4; j++)
                    acc[i][j] = fmaf(a[i], b[j], acc[i][j]);
        }
        __syncthreads();
    }
#pragma unroll
    for (int i = 0; i < 4; i++) {
        float4 v = make_float4(acc[i][0], acc[i][1], acc[i][2], acc[i][3]);
        *(float4*)&C[(bm + tr * 4 + i) * Dn + bn + tc * 4] = v;
    }
}

// ---------------------------------------------------------------------------
// Kernel B: fused bilinear + geo-MLP + mask epilogue.
// One 16x16 output tile per block (256 threads, 1 pair/thread).
// ---------------------------------------------------------------------------
__device__ __forceinline__ float silu_f(float x) {
    return __fdividef(x, 1.f + __expf(-x));
}

__global__ __launch_bounds__(256) void edge_head_kernel(
    const float* __restrict__ q,        // [B,Q,D]
    const float* __restrict__ coords,   // [B,Q,2]
    const int* __restrict__ amask,      // [B,Q] int32 (0/1)  <-- dtype fix
    const float* __restrict__ w1,       // [6,64]
    const float* __restrict__ b1,       // [64]
    const float* __restrict__ w2,       // [64,64]
    const float* __restrict__ b2,       // [64]
    const float* __restrict__ w3,       // [64]
    const float* __restrict__ b3,       // [1]
    const float* __restrict__ bias,     // [1]
    const float* __restrict__ qW,       // [B,Q,D]
    float* __restrict__ out)            // [B,Q,Q]
{
    __shared__ float w1s[6 * GH];
    __shared__ float b1s[GH], b2s[GH], w3s[GH];
    __shared__ float w2s[GH * GH];
    __shared__ float qWs[16][68];
    __shared__ float qs[16][68];
    __shared__ float cxq[16], cyq[16], cxk[16], cyk[16];
    __shared__ int aq[16], ak[16];
    __shared__ float cb3, cbias;

    const int tid = threadIdx.x;
    const int b   = blockIdx.z;
    const int q0  = blockIdx.y * 16;
    const int k0  = blockIdx.x * 16;
    const int tx  = tid & 15;   // k within tile
    const int ty  = tid >> 4;   // qi within tile

    // ---- stage weights / per-tile scalars into smem ----
    for (int i = tid; i < 6 * GH; i += 256) w1s[i] = w1[i];
    for (int i = tid; i < GH * GH; i += 256) w2s[i] = w2[i];
    if (tid < GH) { b1s[tid] = b1[tid]; b2s[tid] = b2[tid]; w3s[tid] = w3[tid]; }
    if (tid == 0) { cb3 = b3[0]; cbias = bias[0]; }
    if (tid < 16) {
        int gq = b * Qn + q0 + tid;
        int gk = b * Qn + k0 + tid;
        cxq[tid] = coords[gq * 2 + 0]; cyq[tid] = coords[gq * 2 + 1];
        cxk[tid] = coords[gk * 2 + 0]; cyk[tid] = coords[gk * 2 + 1];
        aq[tid] = amask[gq];           ak[tid] = amask[gk];
    }
    __syncthreads();

    // ---- bilinear: bil = qW[b,qi,:] . q[b,k,:] over D=256, chunks of 64 ----
    float bil = 0.f;
    const int lr = tid >> 4;          // row 0..15 for loads
    const int lc = (tid & 15) * 4;    // col offset for loads
    for (int d0 = 0; d0 < Dn; d0 += 64) {
        *(float4*)&qWs[lr][lc] = *(const float4*)&qW[(b * Qn + q0 + lr) * Dn + d0 + lc];
        *(float4*)&qs[lr][lc]  = *(const float4*)&q[(b * Qn + k0 + lr) * Dn + d0 + lc];
        __syncthreads();
#pragma unroll
        for (int i = 0; i < 64; i += 4) {
            float4 a = *(const float4*)&qWs[ty][i];
            float4 x = *(const float4*)&qs[tx][i];
            bil = fmaf(a.x, x.x, bil);
            bil = fmaf(a.y, x.y, bil);
            bil = fmaf(a.z, x.z, bil);
            bil = fmaf(a.w, x.w, bil);
        }
        __syncthreads();
    }

    // ---- mask / activity ----
    const bool act = (aq[ty] != 0) && (ak[tx] != 0);
    float val = 0.f;

    if (__any_sync(0xffffffffu, act)) {
        // ---- pairwise geometry features ----
        float dx = cxq[ty] - cxk[tx];
        float dy = cyq[ty] - cyk[tx];
        float dist2 = fmaf(dx, dx, dy * dy);
        float dist  = sqrtf(dist2 + 1e-8f);
        bool  mz    = (fabsf(dx) < 1e-6f) && (fabsf(dy) < 1e-6f);
        float dxs   = mz ? 1e-6f : dx;
        float dys   = mz ? 1e-6f : dy;
        // sin(atan2(dys,dxs)) = dys/hyp, cos(...) = dxs/hyp
        float rh = rsqrtf(fmaf(dxs, dxs, dys * dys));
        float sa = dys * rh;
        float ca = dxs * rh;

        // ---- MLP: 6 -> 64 -> 64 -> 1, streamed layer2 accumulation ----
        float h2[GH];
#pragma unroll
        for (int j = 0; j < GH; j++) h2[j] = b2s[j];

#pragma unroll 2
        for (int i = 0; i < GH; i++) {
            float a = b1s[i];
            a = fmaf(dx,    w1s[0 * GH + i], a);
            a = fmaf(dy,    w1s[1 * GH + i], a);
            a = fmaf(dist,  w1s[2 * GH + i], a);
            a = fmaf(dist2, w1s[3 * GH + i], a);
            a = fmaf(sa,    w1s[4 * GH + i], a);
            a = fmaf(ca,    w1s[5 * GH + i], a);
            float h = silu_f(a);
            const float4* w2row = (const float4*)&w2s[i * GH];
#pragma unroll
            for (int j4 = 0; j4 < GH / 4; j4++) {
                float4 w = w2row[j4];
                h2[4 * j4 + 0] = fmaf(h, w.x, h2[4 * j4 + 0]);
                h2[4 * j4 + 1] = fmaf(h, w.y, h2[4 * j4 + 1]);
                h2[4 * j4 + 2] = fmaf(h, w.z, h2[4 * j4 + 2]);
                h2[4 * j4 + 3] = fmaf(h, w.w, h2[4 * j4 + 3]);
            }
        }

        val = bil + cb3 + cbias;
#pragma unroll
        for (int j = 0; j < GH; j++)
            val = fmaf(silu_f(h2[j]), w3s[j], val);
    }

    const int qi = q0 + ty;
    const int ki = k0 + tx;
    float res = act ? ((qi == ki) ? 0.f : val) : -1e9f;
    out[(((long)b * Qn) + qi) * (long)Qn + ki] = res;
}

// ---------------------------------------------------------------------------
extern "C" void kernel_launch(void* const* d_in, const int* in_sizes, int n_in,
                              void* d_out, int out_size)
{
    const float* q      = (const float*)d_in[0];
    const float* coords = (const float*)d_in[1];
    const int*   amask  = (const int*)d_in[2];     // int32 mask (dtype fix)
    const float* W      = (const float*)d_in[3];
    const float* w1     = (const float*)d_in[4];
    const float* b1     = (const float*)d_in[5];
    const float* w2     = (const float*)d_in[6];
    const float* b2     = (const float*)d_in[7];
    const float* w3     = (const float*)d_in[8];
    const float* b3     = (const float*)d_in[9];
    const float* bias   = (const float*)d_in[10];
    float* out = (float*)d_out;

    float* qWscratch;
    cudaGetSymbolAddress((void**)&qWscratch, g_qW);

    // Kernel A: qW = q @ W
    {
        dim3 grid((Bn * Qn) / 64, Dn / 64);
        qw_gemm_kernel<<<grid, 256>>>(q, W, qWscratch);
    }
    // Kernel B: fused edge head
    {
        dim3 grid(Qn / 16, Qn / 16, Bn);
        edge_head_kernel<<<grid, 256>>>(q, coords, amask,
                                        w1, b1, w2, b2, w3, b3, bias,
                                        qWscratch, out);
    }
}

// round 6
// speedup vs baseline: 1.0748x; 1.0748x over previous
#include <cuda_runtime.h>
#include <cuda_bf16.h>
#include <math.h>

#define Bn 4
#define Qn 1024
#define Dn 256
#define GH 64

typedef unsigned long long ull;

#define FMA2(d, a, b, c) \
    asm("fma.rn.f32x2 %0, %1, %2, %3;" : "=l"(d) : "l"(a), "l"(b), "l"(c))
#define PACK2(d, lo, hi) \
    asm("mov.b64 %0, {%1, %2};" : "=l"(d) : "f"(lo), "f"(hi))
#define UNPACK2(lo, hi, v) \
    asm("mov.b64 {%0, %1}, %2;" : "=f"(lo), "=f"(hi) : "l"(v))

// scratch for qW = q @ W : [B*Q, D] = 4MB
__device__ float g_qW[Bn * Qn * Dn];

// ---------------------------------------------------------------------------
// Kernel A: qW = q @ W.  (small: ~2.7% of total work)
// ---------------------------------------------------------------------------
__global__ __launch_bounds__(256) void qw_gemm_kernel(
    const float* __restrict__ A, const float* __restrict__ Wm, float* __restrict__ C)
{
    __shared__ float As[16][65];
    __shared__ float Bs[16][68];
    const int tid = threadIdx.x;
    const int bm = blockIdx.x * 64, bn = blockIdx.y * 64;
    const int tr = tid >> 4, tc = tid & 15;
    float acc[4][4];
#pragma unroll
    for (int i = 0; i < 4; i++)
#pragma unroll
        for (int j = 0; j < 4; j++) acc[i][j] = 0.f;

    for (int k0 = 0; k0 < Dn; k0 += 16) {
        {
            int m = tid >> 2, kk = (tid & 3) * 4;
            float4 v = *(const float4*)&A[(bm + m) * Dn + k0 + kk];
            As[kk + 0][m] = v.x; As[kk + 1][m] = v.y;
            As[kk + 2][m] = v.z; As[kk + 3][m] = v.w;
        }
        {
            int kk = tid >> 4, n = (tid & 15) * 4;
            *(float4*)&Bs[kk][n] = *(const float4*)&Wm[(k0 + kk) * Dn + bn + n];
        }
        __syncthreads();
#pragma unroll
        for (int kk = 0; kk < 16; kk++) {
            float a[4];
            float4 b4 = *(const float4*)&Bs[kk][tc * 4];
            float b[4] = { b4.x, b4.y, b4.z, b4.w };
#pragma unroll
            for (int i = 0; i < 4; i++) a[i] = As[kk][tr * 4 + i];
#pragma unroll
            for (int i = 0; i < 4; i++)
#pragma unroll
                for (int j = 0; j < 4; j++)
                    acc[i][j] = fmaf(a[i], b[j], acc[i][j]);
        }
        __syncthreads();
    }
#pragma unroll
    for (int i = 0; i < 4; i++) {
        float4 v = make_float4(acc[i][0], acc[i][1], acc[i][2], acc[i][3]);
        *(float4*)&C[(bm + tr * 4 + i) * Dn + bn + tc * 4] = v;
    }
}

// ---------------------------------------------------------------------------
// Kernel B: fused edge head. 32x16 output tile, 256 threads.
// Each thread handles pairs (q0+ty, k) and (q0+16+ty, k).
// Layer-2 vectorized over adjacent j via fma.rn.f32x2 (FFMA2).
// ---------------------------------------------------------------------------
__device__ __forceinline__ float silu_f(float x) {
    return __fdividef(x, 1.f + __expf(-x));
}

__global__ __launch_bounds__(256) void edge_head_kernel(
    const float* __restrict__ q,
    const float* __restrict__ coords,
    const int*   __restrict__ amask,
    const float* __restrict__ w1,   // [6,64]
    const float* __restrict__ b1,   // [64]
    const float* __restrict__ w2,   // [64,64]
    const float* __restrict__ b2,   // [64]
    const float* __restrict__ w3,   // [64]
    const float* __restrict__ b3,
    const float* __restrict__ bias,
    const float* __restrict__ qW,
    float* __restrict__ out)
{
    __shared__ __align__(16) float  w2s[GH * GH];   // 16 KB
    __shared__ float4 w1qA[GH];              // (w1[0][i],w1[1][i],w1[2][i],w1[3][i])
    __shared__ float4 w1qB[GH];              // (w1[4][i],w1[5][i],b1[i],0)
    __shared__ __align__(16) float  b2s[GH];
    __shared__ float  w3s[GH];
    __shared__ __align__(16) float  qWs[32][68];
    __shared__ __align__(16) float  qs[16][68];
    __shared__ float  cxq[32], cyq[32], cxk[16], cyk[16];
    __shared__ int    aqm[32], akm[16];
    __shared__ float  cb3, cbias;

    const int tid = threadIdx.x;
    const int b   = blockIdx.z;
    const int q0  = blockIdx.y * 32;
    const int k0  = blockIdx.x * 16;
    const int tx  = tid & 15;   // k within tile
    const int ty  = tid >> 4;   // 0..15 ; pairs use q rows ty and ty+16

    // ---- stage weights ----
    for (int idx = tid; idx < GH * GH / 4; idx += 256)
        ((float4*)w2s)[idx] = ((const float4*)w2)[idx];
    if (tid < GH) {
        int i = tid;
        w1qA[i] = make_float4(w1[i], w1[GH + i], w1[2 * GH + i], w1[3 * GH + i]);
        w1qB[i] = make_float4(w1[4 * GH + i], w1[5 * GH + i], b1[i], 0.f);
        b2s[i] = b2[i];
        w3s[i] = w3[i];
    }
    if (tid == 0) { cb3 = b3[0]; cbias = bias[0]; }
    if (tid < 32) {
        int gq = b * Qn + q0 + tid;
        cxq[tid] = coords[gq * 2 + 0]; cyq[tid] = coords[gq * 2 + 1];
        aqm[tid] = amask[gq];
    } else if (tid < 48) {
        int t = tid - 32;
        int gk = b * Qn + k0 + t;
        cxk[t] = coords[gk * 2 + 0]; cyk[t] = coords[gk * 2 + 1];
        akm[t] = amask[gk];
    }
    __syncthreads();

    // ---- bilinear for both pairs ----
    float bil0 = 0.f, bil1 = 0.f;
    for (int d0 = 0; d0 < Dn; d0 += 64) {
        // stage qW rows q0..q0+31 (512 float4) and q rows k0..k0+15 (256 float4)
        {
            int t = tid;                 // 0..255 -> first 256 of qW
            int r = t >> 4, c = (t & 15) * 4;
            *(float4*)&qWs[r][c] = *(const float4*)&qW[(b * Qn + q0 + r) * Dn + d0 + c];
            r = (t + 256) >> 4; c = ((t + 256) & 15) * 4;
            *(float4*)&qWs[r][c] = *(const float4*)&qW[(b * Qn + q0 + r) * Dn + d0 + c];
            r = t >> 4; c = (t & 15) * 4;
            *(float4*)&qs[r][c]  = *(const float4*)&q[(b * Qn + k0 + r) * Dn + d0 + c];
        }
        __syncthreads();
#pragma unroll
        for (int i = 0; i < 64; i += 4) {
            float4 x  = *(const float4*)&qs[tx][i];
            float4 a0 = *(const float4*)&qWs[ty][i];
            float4 a1 = *(const float4*)&qWs[ty + 16][i];
            bil0 = fmaf(a0.x, x.x, bil0); bil0 = fmaf(a0.y, x.y, bil0);
            bil0 = fmaf(a0.z, x.z, bil0); bil0 = fmaf(a0.w, x.w, bil0);
            bil1 = fmaf(a1.x, x.x, bil1); bil1 = fmaf(a1.y, x.y, bil1);
            bil1 = fmaf(a1.z, x.z, bil1); bil1 = fmaf(a1.w, x.w, bil1);
        }
        __syncthreads();
    }

    // ---- activity ----
    const bool act0 = (aqm[ty] != 0)      && (akm[tx] != 0);
    const bool act1 = (aqm[ty + 16] != 0) && (akm[tx] != 0);
    float val0 = 0.f, val1 = 0.f;

    if (__any_sync(0xffffffffu, act0 || act1)) {
        // ---- geometry features for both pairs ----
        float kx = cxk[tx], ky = cyk[tx];
        float dx0 = cxq[ty] - kx,      dy0 = cyq[ty] - ky;
        float dx1 = cxq[ty + 16] - kx, dy1 = cyq[ty + 16] - ky;

        float dist20 = fmaf(dx0, dx0, dy0 * dy0);
        float dist21 = fmaf(dx1, dx1, dy1 * dy1);
        float dist0 = sqrtf(dist20 + 1e-8f);
        float dist1 = sqrtf(dist21 + 1e-8f);
        bool mz0 = (fabsf(dx0) < 1e-6f) && (fabsf(dy0) < 1e-6f);
        bool mz1 = (fabsf(dx1) < 1e-6f) && (fabsf(dy1) < 1e-6f);
        float dxs0 = mz0 ? 1e-6f : dx0, dys0 = mz0 ? 1e-6f : dy0;
        float dxs1 = mz1 ? 1e-6f : dx1, dys1 = mz1 ? 1e-6f : dy1;
        float rh0 = rsqrtf(fmaf(dxs0, dxs0, dys0 * dys0));
        float rh1 = rsqrtf(fmaf(dxs1, dxs1, dys1 * dys1));
        float sa0 = dys0 * rh0, ca0 = dxs0 * rh0;
        float sa1 = dys1 * rh1, ca1 = dxs1 * rh1;

        // ---- h2 accumulators: 32 f32x2 per pair (lanes = adjacent j) ----
        ull h2a[GH / 2], h2b[GH / 2];
        const ull* b2v = (const ull*)b2s;   // (b2[2j], b2[2j+1]) pairs
#pragma unroll
        for (int j2 = 0; j2 < GH / 2; j2++) { h2a[j2] = b2v[j2]; h2b[j2] = b2v[j2]; }

#pragma unroll 2
        for (int i = 0; i < GH; i++) {
            // layer-1 (scalar, both pairs)
            float4 wA = w1qA[i];
            float4 wB = w1qB[i];
            float a0 = wB.z;
            a0 = fmaf(dx0, wA.x, a0);  a0 = fmaf(dy0, wA.y, a0);
            a0 = fmaf(dist0, wA.z, a0); a0 = fmaf(dist20, wA.w, a0);
            a0 = fmaf(sa0, wB.x, a0);  a0 = fmaf(ca0, wB.y, a0);
            float a1 = wB.z;
            a1 = fmaf(dx1, wA.x, a1);  a1 = fmaf(dy1, wA.y, a1);
            a1 = fmaf(dist1, wA.z, a1); a1 = fmaf(dist21, wA.w, a1);
            a1 = fmaf(sa1, wB.x, a1);  a1 = fmaf(ca1, wB.y, a1);
            float h0 = silu_f(a0);
            float h1 = silu_f(a1);
            ull H0, H1;
            PACK2(H0, h0, h0);
            PACK2(H1, h1, h1);

            // layer-2: h2 += h * w2[i][:]   (f32x2 over j, LDS.128 feeds 2 f32x2)
            const float* w2row = &w2s[i * GH];
#pragma unroll
            for (int j4 = 0; j4 < GH / 4; j4++) {
                longlong2 wv = *(const longlong2*)(w2row + 4 * j4);
                ull wlo = (ull)wv.x, whi = (ull)wv.y;
                FMA2(h2a[2 * j4],     H0, wlo, h2a[2 * j4]);
                FMA2(h2a[2 * j4 + 1], H0, whi, h2a[2 * j4 + 1]);
                FMA2(h2b[2 * j4],     H1, wlo, h2b[2 * j4]);
                FMA2(h2b[2 * j4 + 1], H1, whi, h2b[2 * j4 + 1]);
            }
        }

        // ---- layer-3 ----
        val0 = bil0 + cb3 + cbias;
        val1 = bil1 + cb3 + cbias;
#pragma unroll
        for (int j2 = 0; j2 < GH / 2; j2++) {
            float e0, e1, f0, f1;
            UNPACK2(e0, e1, h2a[j2]);
            UNPACK2(f0, f1, h2b[j2]);
            float w3lo = w3s[2 * j2], w3hi = w3s[2 * j2 + 1];
            val0 = fmaf(silu_f(e0), w3lo, val0);
            val0 = fmaf(silu_f(e1), w3hi, val0);
            val1 = fmaf(silu_f(f0), w3lo, val1);
            val1 = fmaf(silu_f(f1), w3hi, val1);
        }
    }

    const int ki  = k0 + tx;
    const int qi0 = q0 + ty;
    const int qi1 = q0 + ty + 16;
    float r0 = act0 ? ((qi0 == ki) ? 0.f : val0) : -1e9f;
    float r1 = act1 ? ((qi1 == ki) ? 0.f : val1) : -1e9f;
    out[(((long)b * Qn) + qi0) * (long)Qn + ki] = r0;
    out[(((long)b * Qn) + qi1) * (long)Qn + ki] = r1;
}

// ---------------------------------------------------------------------------
extern "C" void kernel_launch(void* const* d_in, const int* in_sizes, int n_in,
                              void* d_out, int out_size)
{
    const float* q      = (const float*)d_in[0];
    const float* coords = (const float*)d_in[1];
    const int*   amask  = (const int*)d_in[2];
    const float* W      = (const float*)d_in[3];
    const float* w1     = (const float*)d_in[4];
    const float* b1     = (const float*)d_in[5];
    const float* w2     = (const float*)d_in[6];
    const float* b2     = (const float*)d_in[7];
    const float* w3     = (const float*)d_in[8];
    const float* b3     = (const float*)d_in[9];
    const float* bias   = (const float*)d_in[10];
    float* out = (float*)d_out;

    float* qWscratch;
    cudaGetSymbolAddress((void**)&qWscratch, g_qW);

    {
        dim3 grid((Bn * Qn) / 64, Dn / 64);
        qw_gemm_kernel<<<grid, 256>>>(q, W, qWscratch);
    }
    {
        dim3 grid(Qn / 16, Qn / 32, Bn);
        edge_head_kernel<<<grid, 256>>>(q, coords, amask,
                                        w1, b1, w2, b2, w3, b3, bias,
                                        qWscratch, out);
    }
}

// round 7
// speedup vs baseline: 4.2072x; 3.9145x over previous
#include <cuda_runtime.h>
#include <cuda_bf16.h>
#include <math.h>

#define Bn 4
#define Qn 1024
#define Dn 256
#define GH 64
#define TQ 64
#define TK 64
#define PITCH 72    // bf16 pitch for q/qW smem tiles (conflict-free mma gathers)
#define BPITCH 66   // fp32 pitch for bil staging

typedef unsigned int uint;

// bf16 copies of qW = q@W and q (prep kernel output)
__device__ __nv_bfloat16 g_qWb[Bn * Qn * Dn];
__device__ __nv_bfloat16 g_qb[Bn * Qn * Dn];

__device__ __forceinline__ uint packbf2(float lo, float hi) {
    uint r;
    asm("cvt.rn.bf16x2.f32 %0, %1, %2;" : "=r"(r) : "f"(hi), "f"(lo));
    return r;
}

__device__ __forceinline__ float silu_f(float x) {
    // x * sigmoid(x); sigmoid via HW tanh: 1 MUFU
    float t;
    asm("tanh.approx.f32 %0, %1;" : "=f"(t) : "f"(0.5f * x));
    return x * fmaf(0.5f, t, 0.5f);
}

__device__ __forceinline__ void mma16816(float* c, uint a0, uint a1, uint a2, uint a3,
                                         uint b0, uint b1) {
    asm("mma.sync.aligned.m16n8k16.row.col.f32.bf16.bf16.f32 "
        "{%0,%1,%2,%3},{%4,%5,%6,%7},{%8,%9},{%0,%1,%2,%3};"
        : "+f"(c[0]), "+f"(c[1]), "+f"(c[2]), "+f"(c[3])
        : "r"(a0), "r"(a1), "r"(a2), "r"(a3), "r"(b0), "r"(b1));
}

__device__ __forceinline__ float l1act(float4 A, float4 Bv,
                                       float dx, float dy, float ds, float d2,
                                       float sa, float ca) {
    float t = Bv.z;
    t = fmaf(dx, A.x, t); t = fmaf(dy, A.y, t);
    t = fmaf(ds, A.z, t); t = fmaf(d2, A.w, t);
    t = fmaf(sa, Bv.x, t); t = fmaf(ca, Bv.y, t);
    return t;
}

// ---------------------------------------------------------------------------
// Prep kernel: qW = q @ W (fp32 math) -> bf16; also q -> bf16.
// ---------------------------------------------------------------------------
__global__ __launch_bounds__(256) void prep_kernel(
    const float* __restrict__ A, const float* __restrict__ Wm)
{
    __shared__ float As[16][65];
    __shared__ float Bs[16][68];
    const int tid = threadIdx.x;
    const int bm = blockIdx.x * 64, bn = blockIdx.y * 64;
    const int tr = tid >> 4, tc = tid & 15;
    float acc[4][4];
#pragma unroll
    for (int i = 0; i < 4; i++)
#pragma unroll
        for (int j = 0; j < 4; j++) acc[i][j] = 0.f;

    for (int k0 = 0; k0 < Dn; k0 += 16) {
        {
            int mm = tid >> 2, kk = (tid & 3) * 4;
            float4 v = *(const float4*)&A[(bm + mm) * Dn + k0 + kk];
            As[kk + 0][mm] = v.x; As[kk + 1][mm] = v.y;
            As[kk + 2][mm] = v.z; As[kk + 3][mm] = v.w;
        }
        {
            int kk = tid >> 4, n = (tid & 15) * 4;
            *(float4*)&Bs[kk][n] = *(const float4*)&Wm[(k0 + kk) * Dn + bn + n];
        }
        __syncthreads();
#pragma unroll
        for (int kk = 0; kk < 16; kk++) {
            float a[4];
            float4 b4 = *(const float4*)&Bs[kk][tc * 4];
            float b[4] = { b4.x, b4.y, b4.z, b4.w };
#pragma unroll
            for (int i = 0; i < 4; i++) a[i] = As[kk][tr * 4 + i];
#pragma unroll
            for (int i = 0; i < 4; i++)
#pragma unroll
                for (int j = 0; j < 4; j++)
                    acc[i][j] = fmaf(a[i], b[j], acc[i][j]);
        }
        __syncthreads();
    }
#pragma unroll
    for (int i = 0; i < 4; i++) {
        int row = bm + tr * 4 + i, col = bn + tc * 4;
        __nv_bfloat162 p0 = __floats2bfloat162_rn(acc[i][0], acc[i][1]);
        __nv_bfloat162 p1 = __floats2bfloat162_rn(acc[i][2], acc[i][3]);
        *(__nv_bfloat162*)&g_qWb[row * Dn + col]     = p0;
        *(__nv_bfloat162*)&g_qWb[row * Dn + col + 2] = p1;
    }
    // convert this tile of q -> bf16
    for (int i = tid; i < 64 * 32; i += 256) {
        int r = i >> 5, c2 = (i & 31) * 2;
        float2 v = *(const float2*)&A[(bm + r) * Dn + bn + c2];
        *(__nv_bfloat162*)&g_qb[(bm + r) * Dn + bn + c2] = __floats2bfloat162_rn(v.x, v.y);
    }
}

// ---------------------------------------------------------------------------
// Fused kernel: bilinear (mma) + geo MLP (mma layer2) + mask epilogue.
// 64x64 output tile, 8 warps: warp = (wq = w%4: 16 q-rows) x (wk = w/4: 32 k-cols).
// ---------------------------------------------------------------------------
__global__ __launch_bounds__(256) void edge_head_mma_kernel(
    const float* __restrict__ coords,
    const int*   __restrict__ amask,
    const float* __restrict__ w1,   // [6,64]
    const float* __restrict__ b1,   // [64]
    const float* __restrict__ w2,   // [64,64]
    const float* __restrict__ b2,   // [64]
    const float* __restrict__ w3,   // [64]
    const float* __restrict__ b3,
    const float* __restrict__ bias,
    float* __restrict__ out)
{
    __shared__ __align__(16) __nv_bfloat16 qWt[TQ * PITCH];
    __shared__ __align__(16) __nv_bfloat16 qt[TK * PITCH];
    __shared__ float  bilS[TQ * BPITCH];
    __shared__ float4 w1A[GH], w1B[GH];
    __shared__ float  cxq[TQ], cyq[TQ], cxk[TK], cyk[TK];
    __shared__ int    aqs[TQ], aks[TK];
    __shared__ float  cadd;

    const int tid  = threadIdx.x;
    const int warp = tid >> 5;
    const int lane = tid & 31;
    const int m    = lane & 3;       // fragment col group
    const int g    = lane >> 2;      // fragment row group (0..7)
    const int wq   = warp & 3;       // q sub-tile (16 rows)
    const int wk   = warp >> 2;      // k sub-tile (32 cols)
    const int b    = blockIdx.z;
    const int q0   = blockIdx.y * TQ;
    const int k0   = blockIdx.x * TK;

    // ---- stage small stuff ----
    if (tid < GH) {
        int i = tid;
        w1A[i] = make_float4(w1[i], w1[GH + i], w1[2 * GH + i], w1[3 * GH + i]);
        w1B[i] = make_float4(w1[4 * GH + i], w1[5 * GH + i], b1[i], 0.f);
        int gq = b * Qn + q0 + i;
        cxq[i] = coords[gq * 2 + 0]; cyq[i] = coords[gq * 2 + 1];
        aqs[i] = amask[gq];
    } else if (tid < 2 * GH) {
        int i = tid - GH;
        int gk = b * Qn + k0 + i;
        cxk[i] = coords[gk * 2 + 0]; cyk[i] = coords[gk * 2 + 1];
        aks[i] = amask[gk];
    }
    if (tid == 0) cadd = b3[0] + bias[0];

    // ---- preload w2 B-fragments (register-resident for entire kernel) ----
    uint B2[4][8][2];
#pragma unroll
    for (int s = 0; s < 4; s++) {
#pragma unroll
        for (int n = 0; n < 8; n++) {
            int kk = 16 * s + 2 * m;
            int nn = 8 * n + g;
            B2[s][n][0] = packbf2(w2[kk * GH + nn],       w2[(kk + 1) * GH + nn]);
            B2[s][n][1] = packbf2(w2[(kk + 8) * GH + nn], w2[(kk + 9) * GH + nn]);
        }
    }
    float2 w3p[8], b2p[8];
#pragma unroll
    for (int n = 0; n < 8; n++) {
        w3p[n] = *(const float2*)&w3[8 * n + 2 * m];
        b2p[n] = *(const float2*)&b2[8 * n + 2 * m];
    }

    // ---- bilinear via mma: bil[q,k] = sum_d qW[q,d] * q[k,d] ----
    float bacc[4][4];
#pragma unroll
    for (int n = 0; n < 4; n++)
#pragma unroll
        for (int j = 0; j < 4; j++) bacc[n][j] = 0.f;

#pragma unroll 1
    for (int d0 = 0; d0 < Dn; d0 += 64) {
        __syncthreads();
        // stage 64x64 bf16 tiles (8 uint4 per row)
#pragma unroll
        for (int rep = 0; rep < 2; rep++) {
            int idx = tid + rep * 256;
            int r = idx >> 3, c8 = (idx & 7) * 8;
            *(uint4*)&qWt[r * PITCH + c8] =
                *(const uint4*)&g_qWb[(b * Qn + q0 + r) * Dn + d0 + c8];
            *(uint4*)&qt[r * PITCH + c8] =
                *(const uint4*)&g_qb[(b * Qn + k0 + r) * Dn + d0 + c8];
        }
        __syncthreads();
#pragma unroll
        for (int s2 = 0; s2 < 4; s2++) {
            const int acol = 16 * s2 + 2 * m;
            const int arow = 16 * wq + g;
            uint a0 = *(const uint*)&qWt[arow * PITCH + acol];
            uint a1 = *(const uint*)&qWt[(arow + 8) * PITCH + acol];
            uint a2 = *(const uint*)&qWt[arow * PITCH + acol + 8];
            uint a3 = *(const uint*)&qWt[(arow + 8) * PITCH + acol + 8];
#pragma unroll
            for (int n = 0; n < 4; n++) {
                const int brow = 32 * wk + 8 * n + g;
                uint b0 = *(const uint*)&qt[brow * PITCH + acol];
                uint b1 = *(const uint*)&qt[brow * PITCH + acol + 8];
                mma16816(bacc[n], a0, a1, a2, a3, b0, b1);
            }
        }
    }
    __syncthreads();
    // stage bil to smem (layout handoff: mma frag -> row/col addressable)
#pragma unroll
    for (int n = 0; n < 4; n++) {
        int row = 16 * wq + g;
        int col = 32 * wk + 8 * n + 2 * m;
        *(float2*)&bilS[row * BPITCH + col]       = make_float2(bacc[n][0], bacc[n][1]);
        *(float2*)&bilS[(row + 8) * BPITCH + col] = make_float2(bacc[n][2], bacc[n][3]);
    }
    __syncthreads();

    // ---- MLP phase: chunks of 16 q-rows x 1 k ----
    const int row0 = 16 * wq + g;       // tile-local q rows owned by this thread
    const int row1 = row0 + 8;
    const float qx0 = cxq[row0], qy0 = cyq[row0];
    const float qx1 = cxq[row1], qy1 = cyq[row1];
    const bool  qa0 = (aqs[row0] != 0), qa1 = (aqs[row1] != 0);
    const float caddv = cadd;

#pragma unroll 1
    for (int kc = 0; kc < 32; kc++) {
        const int k  = 32 * wk + kc;     // tile-local k
        const int gk = k0 + k;           // global k
        const bool kact = (aks[k] != 0);

        if (!kact) {
            if (m == 0) {
                out[((long)(b * Qn + q0 + row0)) * Qn + gk] = -1e9f;
                out[((long)(b * Qn + q0 + row1)) * Qn + gk] = -1e9f;
            }
            continue;
        }

        // geo features for both rows vs this k
        const float kx = cxk[k], ky = cyk[k];
        float dx0 = qx0 - kx, dy0 = qy0 - ky;
        float dx1 = qx1 - kx, dy1 = qy1 - ky;
        float d20 = fmaf(dx0, dx0, dy0 * dy0);
        float d21 = fmaf(dx1, dx1, dy1 * dy1);
        float ds0 = sqrtf(d20 + 1e-8f);
        float ds1 = sqrtf(d21 + 1e-8f);
        bool mz0 = (fabsf(dx0) < 1e-6f) && (fabsf(dy0) < 1e-6f);
        bool mz1 = (fabsf(dx1) < 1e-6f) && (fabsf(dy1) < 1e-6f);
        float xs0 = mz0 ? 1e-6f : dx0, ys0 = mz0 ? 1e-6f : dy0;
        float xs1 = mz1 ? 1e-6f : dx1, ys1 = mz1 ? 1e-6f : dy1;
        float rh0 = rsqrtf(fmaf(xs0, xs0, ys0 * ys0));
        float rh1 = rsqrtf(fmaf(xs1, xs1, ys1 * ys1));
        float sa0 = ys0 * rh0, ca0 = xs0 * rh0;
        float sa1 = ys1 * rh1, ca1 = xs1 * rh1;

        float acc[8][4];
#pragma unroll
        for (int n = 0; n < 8; n++)
#pragma unroll
            for (int j = 0; j < 4; j++) acc[n][j] = 0.f;

        // layer1 -> A fragments -> layer2 mma
#pragma unroll
        for (int s = 0; s < 4; s++) {
            const int j0 = 16 * s + 2 * m;
            float4 A0 = w1A[j0],     B0 = w1B[j0];
            float4 A1 = w1A[j0 + 1], B1 = w1B[j0 + 1];
            float4 A8 = w1A[j0 + 8], B8 = w1B[j0 + 8];
            float4 A9 = w1A[j0 + 9], B9 = w1B[j0 + 9];
            float h00 = silu_f(l1act(A0, B0, dx0, dy0, ds0, d20, sa0, ca0));
            float h01 = silu_f(l1act(A1, B1, dx0, dy0, ds0, d20, sa0, ca0));
            float h10 = silu_f(l1act(A0, B0, dx1, dy1, ds1, d21, sa1, ca1));
            float h11 = silu_f(l1act(A1, B1, dx1, dy1, ds1, d21, sa1, ca1));
            float h02 = silu_f(l1act(A8, B8, dx0, dy0, ds0, d20, sa0, ca0));
            float h03 = silu_f(l1act(A9, B9, dx0, dy0, ds0, d20, sa0, ca0));
            float h12 = silu_f(l1act(A8, B8, dx1, dy1, ds1, d21, sa1, ca1));
            float h13 = silu_f(l1act(A9, B9, dx1, dy1, ds1, d21, sa1, ca1));
            uint a0 = packbf2(h00, h01);
            uint a1 = packbf2(h10, h11);
            uint a2 = packbf2(h02, h03);
            uint a3 = packbf2(h12, h13);
#pragma unroll
            for (int n = 0; n < 8; n++)
                mma16816(acc[n], a0, a1, a2, a3, B2[s][n][0], B2[s][n][1]);
        }

        // epilogue: silu(H2 + b2) . w3, reduce across 4-lane group
        float p0 = 0.f, p1 = 0.f;
#pragma unroll
        for (int n = 0; n < 8; n++) {
            p0 = fmaf(silu_f(acc[n][0] + b2p[n].x), w3p[n].x, p0);
            p0 = fmaf(silu_f(acc[n][1] + b2p[n].y), w3p[n].y, p0);
            p1 = fmaf(silu_f(acc[n][2] + b2p[n].x), w3p[n].x, p1);
            p1 = fmaf(silu_f(acc[n][3] + b2p[n].y), w3p[n].y, p1);
        }
        p0 += __shfl_xor_sync(0xffffffffu, p0, 1);
        p0 += __shfl_xor_sync(0xffffffffu, p0, 2);
        p1 += __shfl_xor_sync(0xffffffffu, p1, 1);
        p1 += __shfl_xor_sync(0xffffffffu, p1, 2);

        if (m == 0) {
            const int qi0 = q0 + row0, qi1 = q0 + row1;
            float v0 = (qa0) ? ((qi0 == gk) ? 0.f
                               : p0 + bilS[row0 * BPITCH + k] + caddv) : -1e9f;
            float v1 = (qa1) ? ((qi1 == gk) ? 0.f
                               : p1 + bilS[row1 * BPITCH + k] + caddv) : -1e9f;
            out[((long)(b * Qn + qi0)) * Qn + gk] = v0;
            out[((long)(b * Qn + qi1)) * Qn + gk] = v1;
        }
    }
}

// ---------------------------------------------------------------------------
extern "C" void kernel_launch(void* const* d_in, const int* in_sizes, int n_in,
                              void* d_out, int out_size)
{
    const float* q      = (const float*)d_in[0];
    const float* coords = (const float*)d_in[1];
    const int*   amask  = (const int*)d_in[2];
    const float* W      = (const float*)d_in[3];
    const float* w1     = (const float*)d_in[4];
    const float* b1     = (const float*)d_in[5];
    const float* w2     = (const float*)d_in[6];
    const float* b2     = (const float*)d_in[7];
    const float* w3     = (const float*)d_in[8];
    const float* b3     = (const float*)d_in[9];
    const float* bias   = (const float*)d_in[10];
    float* out = (float*)d_out;

    {
        dim3 grid((Bn * Qn) / 64, Dn / 64);
        prep_kernel<<<grid, 256>>>(q, W);
    }
    {
        dim3 grid(Qn / TK, Qn / TQ, Bn);
        edge_head_mma_kernel<<<grid, 256>>>(coords, amask,
                                            w1, b1, w2, b2, w3, b3, bias, out);
    }
}

// round 8
// speedup vs baseline: 6.9163x; 1.6439x over previous
#include <cuda_runtime.h>
#include <cuda_bf16.h>
#include <math.h>

#define Bn 4
#define Qn 1024
#define Dn 256
#define GH 64
#define TQ 64
#define TK 64
#define PITCH 72    // bf16 pitch for q/qW smem tiles
#define BPITCH 66   // fp32 pitch for bil staging

typedef unsigned int uint;

__device__ __nv_bfloat16 g_qWb[Bn * Qn * Dn];
__device__ __nv_bfloat16 g_qb[Bn * Qn * Dn];

__device__ __forceinline__ uint packbf2(float lo, float hi) {
    uint r;
    asm("cvt.rn.bf16x2.f32 %0, %1, %2;" : "=r"(r) : "f"(hi), "f"(lo));
    return r;
}

__device__ __forceinline__ float silu_f(float x) {
    float t;
    asm("tanh.approx.f32 %0, %1;" : "=f"(t) : "f"(0.5f * x));
    return x * fmaf(0.5f, t, 0.5f);
}

__device__ __forceinline__ void mma16816(float* c, uint a0, uint a1, uint a2, uint a3,
                                         uint b0, uint b1) {
    asm("mma.sync.aligned.m16n8k16.row.col.f32.bf16.bf16.f32 "
        "{%0,%1,%2,%3},{%4,%5,%6,%7},{%8,%9},{%0,%1,%2,%3};"
        : "+f"(c[0]), "+f"(c[1]), "+f"(c[2]), "+f"(c[3])
        : "r"(a0), "r"(a1), "r"(a2), "r"(a3), "r"(b0), "r"(b1));
}

__device__ __forceinline__ void mma16808(float& c0, float& c1, float& c2, float& c3,
                                         uint a0, uint a1, uint b0) {
    asm("mma.sync.aligned.m16n8k8.row.col.f32.bf16.bf16.f32 "
        "{%0,%1,%2,%3},{%4,%5},{%6},{%0,%1,%2,%3};"
        : "+f"(c0), "+f"(c1), "+f"(c2), "+f"(c3)
        : "r"(a0), "r"(a1), "r"(b0));
}

// ---------------------------------------------------------------------------
// Prep kernel: qW = q @ W (fp32 math) -> bf16; also q -> bf16.
// ---------------------------------------------------------------------------
__global__ __launch_bounds__(256) void prep_kernel(
    const float* __restrict__ A, const float* __restrict__ Wm)
{
    __shared__ float As[16][65];
    __shared__ float Bs[16][68];
    const int tid = threadIdx.x;
    const int bm = blockIdx.x * 64, bn = blockIdx.y * 64;
    const int tr = tid >> 4, tc = tid & 15;
    float acc[4][4];
#pragma unroll
    for (int i = 0; i < 4; i++)
#pragma unroll
        for (int j = 0; j < 4; j++) acc[i][j] = 0.f;

    for (int k0 = 0; k0 < Dn; k0 += 16) {
        {
            int mm = tid >> 2, kk = (tid & 3) * 4;
            float4 v = *(const float4*)&A[(bm + mm) * Dn + k0 + kk];
            As[kk + 0][mm] = v.x; As[kk + 1][mm] = v.y;
            As[kk + 2][mm] = v.z; As[kk + 3][mm] = v.w;
        }
        {
            int kk = tid >> 4, n = (tid & 15) * 4;
            *(float4*)&Bs[kk][n] = *(const float4*)&Wm[(k0 + kk) * Dn + bn + n];
        }
        __syncthreads();
#pragma unroll
        for (int kk = 0; kk < 16; kk++) {
            float a[4];
            float4 b4 = *(const float4*)&Bs[kk][tc * 4];
            float b[4] = { b4.x, b4.y, b4.z, b4.w };
#pragma unroll
            for (int i = 0; i < 4; i++) a[i] = As[kk][tr * 4 + i];
#pragma unroll
            for (int i = 0; i < 4; i++)
#pragma unroll
                for (int j = 0; j < 4; j++)
                    acc[i][j] = fmaf(a[i], b[j], acc[i][j]);
        }
        __syncthreads();
    }
#pragma unroll
    for (int i = 0; i < 4; i++) {
        int row = bm + tr * 4 + i, col = bn + tc * 4;
        *(__nv_bfloat162*)&g_qWb[row * Dn + col]     = __floats2bfloat162_rn(acc[i][0], acc[i][1]);
        *(__nv_bfloat162*)&g_qWb[row * Dn + col + 2] = __floats2bfloat162_rn(acc[i][2], acc[i][3]);
    }
    for (int i = tid; i < 64 * 32; i += 256) {
        int r = i >> 5, c2 = (i & 31) * 2;
        float2 v = *(const float2*)&A[(bm + r) * Dn + bn + c2];
        *(__nv_bfloat162*)&g_qb[(bm + r) * Dn + bn + c2] = __floats2bfloat162_rn(v.x, v.y);
    }
}

// ---------------------------------------------------------------------------
// Fused kernel: bilinear (mma) + geo MLP (both layers on mma) + mask epilogue.
// 64x64 tile, 8 warps = 4 (q sub-tiles of 16) x 2 (k sub-tiles of 32).
// ---------------------------------------------------------------------------
__global__ __launch_bounds__(256, 2) void edge_head_mma_kernel(
    const float* __restrict__ coords,
    const int*   __restrict__ amask,
    const float* __restrict__ w1,   // [6,64]
    const float* __restrict__ b1,   // [64]
    const float* __restrict__ w2,   // [64,64]
    const float* __restrict__ b2,   // [64]
    const float* __restrict__ w3,   // [64]
    const float* __restrict__ b3,
    const float* __restrict__ bias,
    float* __restrict__ out)
{
    __shared__ __align__(16) __nv_bfloat16 qWt[TQ * PITCH];
    __shared__ __align__(16) __nv_bfloat16 qt[TK * PITCH];
    __shared__ float  bilS[TQ * BPITCH];
    __shared__ __align__(8) uint2  B2s[4 * 8 * 32];   // layer-2 B frags, 8KB
    __shared__ __align__(8) float2 b1p[32], b2p[32], w3p[32];  // [nb*4+m]
    __shared__ float  cxq[TQ], cyq[TQ], cxk[TK], cyk[TK];
    __shared__ int    aqs[TQ], aks[TK];
    __shared__ float  cadd;

    const int tid  = threadIdx.x;
    const int warp = tid >> 5;
    const int lane = tid & 31;
    const int m    = lane & 3;
    const int g    = lane >> 2;
    const int wq   = warp & 3;
    const int wk   = warp >> 2;
    const int b    = blockIdx.z;
    const int q0   = blockIdx.y * TQ;
    const int k0   = blockIdx.x * TK;

    // ---- stage per-tile scalars ----
    if (tid < GH) {
        int i = tid;
        int gq = b * Qn + q0 + i;
        cxq[i] = coords[gq * 2 + 0]; cyq[i] = coords[gq * 2 + 1];
        aqs[i] = amask[gq];
    } else if (tid < 2 * GH) {
        int i = tid - GH;
        int gk = b * Qn + k0 + i;
        cxk[i] = coords[gk * 2 + 0]; cyk[i] = coords[gk * 2 + 1];
        aks[i] = amask[gk];
    }
    if (tid == 0) cadd = b3[0] + bias[0];

    // ---- build layer-2 B fragments in smem: entry (s,n,lane) ----
    // frag for thread (g,m): b0 = w2[16s+2m][8n+g], w2[16s+2m+1][8n+g]
    //                        b1 = w2[16s+2m+8][8n+g], w2[16s+2m+9][8n+g]
#pragma unroll
    for (int e = tid; e < 1024; e += 256) {
        int s  = e >> 8;
        int n  = (e >> 5) & 7;
        int ln = e & 31;
        int em = ln & 3, eg = ln >> 2;
        int kk = 16 * s + 2 * em;
        int nn = 8 * n + eg;
        uint2 v;
        v.x = packbf2(w2[kk * GH + nn],       w2[(kk + 1) * GH + nn]);
        v.y = packbf2(w2[(kk + 8) * GH + nn], w2[(kk + 9) * GH + nn]);
        B2s[e] = v;
    }
    // bias/w3 packs indexed [nb*4 + m] -> (x = v[8nb+2m], y = v[8nb+2m+1])
    if (tid < 32) {
        int nb = tid >> 2, mm = tid & 3;
        int c = 8 * nb + 2 * mm;
        b1p[tid] = make_float2(b1[c], b1[c + 1]);
        b2p[tid] = make_float2(b2[c], b2[c + 1]);
        w3p[tid] = make_float2(w3[c], w3[c + 1]);
    }

    // ---- layer-1 B fragments (w1, k=8 padded): 8 regs ----
    uint W1B[8];
#pragma unroll
    for (int nb = 0; nb < 8; nb++) {
        int nn = 8 * nb + g;
        W1B[nb] = (m < 3) ? packbf2(w1[(2 * m) * GH + nn], w1[(2 * m + 1) * GH + nn]) : 0u;
    }

    // ---- bilinear via mma ----
    float bacc[4][4];
#pragma unroll
    for (int n = 0; n < 4; n++)
#pragma unroll
        for (int j = 0; j < 4; j++) bacc[n][j] = 0.f;

#pragma unroll 1
    for (int d0 = 0; d0 < Dn; d0 += 64) {
        __syncthreads();
#pragma unroll
        for (int rep = 0; rep < 2; rep++) {
            int idx = tid + rep * 256;
            int r = idx >> 3, c8 = (idx & 7) * 8;
            *(uint4*)&qWt[r * PITCH + c8] =
                *(const uint4*)&g_qWb[(b * Qn + q0 + r) * Dn + d0 + c8];
            *(uint4*)&qt[r * PITCH + c8] =
                *(const uint4*)&g_qb[(b * Qn + k0 + r) * Dn + d0 + c8];
        }
        __syncthreads();
#pragma unroll
        for (int s2 = 0; s2 < 4; s2++) {
            const int acol = 16 * s2 + 2 * m;
            const int arow = 16 * wq + g;
            uint a0 = *(const uint*)&qWt[arow * PITCH + acol];
            uint a1 = *(const uint*)&qWt[(arow + 8) * PITCH + acol];
            uint a2 = *(const uint*)&qWt[arow * PITCH + acol + 8];
            uint a3 = *(const uint*)&qWt[(arow + 8) * PITCH + acol + 8];
#pragma unroll
            for (int n = 0; n < 4; n++) {
                const int brow = 32 * wk + 8 * n + g;
                uint b0 = *(const uint*)&qt[brow * PITCH + acol];
                uint b1v = *(const uint*)&qt[brow * PITCH + acol + 8];
                mma16816(bacc[n], a0, a1, a2, a3, b0, b1v);
            }
        }
    }
    __syncthreads();
#pragma unroll
    for (int n = 0; n < 4; n++) {
        int row = 16 * wq + g;
        int col = 32 * wk + 8 * n + 2 * m;
        *(float2*)&bilS[row * BPITCH + col]       = make_float2(bacc[n][0], bacc[n][1]);
        *(float2*)&bilS[(row + 8) * BPITCH + col] = make_float2(bacc[n][2], bacc[n][3]);
    }
    __syncthreads();

    // ---- MLP phase ----
    const int row0 = 16 * wq + g;
    const int row1 = row0 + 8;
    const float qx0 = cxq[row0], qy0 = cyq[row0];
    const float qx1 = cxq[row1], qy1 = cyq[row1];
    const bool  qa0 = (aqs[row0] != 0), qa1 = (aqs[row1] != 0);
    const float caddv = cadd;

#pragma unroll 1
    for (int kc = 0; kc < 32; kc++) {
        const int k  = 32 * wk + kc;
        const int gk = k0 + k;

        if (aks[k] == 0) {
            if (m == 0) {
                out[((long)(b * Qn + q0 + row0)) * Qn + gk] = -1e9f;
                out[((long)(b * Qn + q0 + row1)) * Qn + gk] = -1e9f;
            }
            continue;
        }

        // geo features (fp32), both rows vs this k
        const float kx = cxk[k], ky = cyk[k];
        float dx0 = qx0 - kx, dy0 = qy0 - ky;
        float dx1 = qx1 - kx, dy1 = qy1 - ky;
        float d20 = fmaf(dx0, dx0, dy0 * dy0);
        float d21 = fmaf(dx1, dx1, dy1 * dy1);
        float ds0 = sqrtf(d20 + 1e-8f);
        float ds1 = sqrtf(d21 + 1e-8f);
        bool mz0 = (fabsf(dx0) < 1e-6f) && (fabsf(dy0) < 1e-6f);
        bool mz1 = (fabsf(dx1) < 1e-6f) && (fabsf(dy1) < 1e-6f);
        float xs0 = mz0 ? 1e-6f : dx0, ys0 = mz0 ? 1e-6f : dy0;
        float xs1 = mz1 ? 1e-6f : dx1, ys1 = mz1 ? 1e-6f : dy1;
        float rh0 = rsqrtf(fmaf(xs0, xs0, ys0 * ys0));
        float rh1 = rsqrtf(fmaf(xs1, xs1, ys1 * ys1));
        float sa0 = ys0 * rh0, ca0 = xs0 * rh0;
        float sa1 = ys1 * rh1, ca1 = xs1 * rh1;

        // pack layer-1 A fragments: feature pair (2m, 2m+1) of rows g, g+8
        float flo0, fhi0, flo1, fhi1;
        if (m == 0)      { flo0 = dx0; fhi0 = dy0; flo1 = dx1; fhi1 = dy1; }
        else if (m == 1) { flo0 = ds0; fhi0 = d20; flo1 = ds1; fhi1 = d21; }
        else if (m == 2) { flo0 = sa0; fhi0 = ca0; flo1 = sa1; fhi1 = ca1; }
        else             { flo0 = 0.f; fhi0 = 0.f; flo1 = 0.f; fhi1 = 0.f; }
        const uint GA0 = packbf2(flo0, fhi0);
        const uint GA1 = packbf2(flo1, fhi1);

        // layer-2 accumulators, b2-initialized
        float acc2[8][4];
#pragma unroll
        for (int n = 0; n < 8; n++) {
            float2 bv = b2p[n * 4 + m];
            acc2[n][0] = bv.x; acc2[n][1] = bv.y;
            acc2[n][2] = bv.x; acc2[n][3] = bv.y;
        }

#pragma unroll
        for (int s = 0; s < 4; s++) {
            uint a0, a1, a2, a3;
            {
                int nb = 2 * s;
                float2 bv = b1p[nb * 4 + m];
                float c0 = bv.x, c1 = bv.y, c2 = bv.x, c3 = bv.y;
                mma16808(c0, c1, c2, c3, GA0, GA1, W1B[nb]);
                a0 = packbf2(silu_f(c0), silu_f(c1));
                a1 = packbf2(silu_f(c2), silu_f(c3));
            }
            {
                int nb = 2 * s + 1;
                float2 bv = b1p[nb * 4 + m];
                float c0 = bv.x, c1 = bv.y, c2 = bv.x, c3 = bv.y;
                mma16808(c0, c1, c2, c3, GA0, GA1, W1B[nb]);
                a2 = packbf2(silu_f(c0), silu_f(c1));
                a3 = packbf2(silu_f(c2), silu_f(c3));
            }
            const uint2* Brow = &B2s[(s * 8) * 32 + lane];
#pragma unroll
            for (int n = 0; n < 8; n++) {
                uint2 Bv = Brow[n * 32];
                mma16816(acc2[n], a0, a1, a2, a3, Bv.x, Bv.y);
            }
        }

        // epilogue: silu(h2) . w3, reduce over m-group
        float p0 = 0.f, p1 = 0.f;
#pragma unroll
        for (int n = 0; n < 8; n++) {
            float2 wv = w3p[n * 4 + m];
            p0 = fmaf(silu_f(acc2[n][0]), wv.x, p0);
            p0 = fmaf(silu_f(acc2[n][1]), wv.y, p0);
            p1 = fmaf(silu_f(acc2[n][2]), wv.x, p1);
            p1 = fmaf(silu_f(acc2[n][3]), wv.y, p1);
        }
        p0 += __shfl_xor_sync(0xffffffffu, p0, 1);
        p0 += __shfl_xor_sync(0xffffffffu, p0, 2);
        p1 += __shfl_xor_sync(0xffffffffu, p1, 1);
        p1 += __shfl_xor_sync(0xffffffffu, p1, 2);

        if (m == 0) {
            const int qi0 = q0 + row0, qi1 = q0 + row1;
            float v0 = qa0 ? ((qi0 == gk) ? 0.f
                              : p0 + bilS[row0 * BPITCH + k] + caddv) : -1e9f;
            float v1 = qa1 ? ((qi1 == gk) ? 0.f
                              : p1 + bilS[row1 * BPITCH + k] + caddv) : -1e9f;
            out[((long)(b * Qn + qi0)) * Qn + gk] = v0;
            out[((long)(b * Qn + qi1)) * Qn + gk] = v1;
        }
    }
}

// ---------------------------------------------------------------------------
extern "C" void kernel_launch(void* const* d_in, const int* in_sizes, int n_in,
                              void* d_out, int out_size)
{
    const float* q      = (const float*)d_in[0];
    const float* coords = (const float*)d_in[1];
    const int*   amask  = (const int*)d_in[2];
    const float* W      = (const float*)d_in[3];
    const float* w1     = (const float*)d_in[4];
    const float* b1     = (const float*)d_in[5];
    const float* w2     = (const float*)d_in[6];
    const float* b2     = (const float*)d_in[7];
    const float* w3     = (const float*)d_in[8];
    const float* b3     = (const float*)d_in[9];
    const float* bias   = (const float*)d_in[10];
    float* out = (float*)d_out;

    {
        dim3 grid((Bn * Qn) / 64, Dn / 64);
        prep_kernel<<<grid, 256>>>(q, W);
    }
    {
        dim3 grid(Qn / TK, Qn / TQ, Bn);
        edge_head_mma_kernel<<<grid, 256>>>(coords, amask,
                                            w1, b1, w2, b2, w3, b3, bias, out);
    }
}

// round 9
// speedup vs baseline: 7.7393x; 1.1190x over previous
#include <cuda_runtime.h>
#include <cuda_bf16.h>
#include <math.h>

#define Bn 4
#define Qn 1024
#define Dn 256
#define GH 64
#define TQ 64
#define TK 64
#define PITCH 72    // bf16 pitch for mma smem tiles
#define BPITCH 66   // fp32 pitch for bil staging

typedef unsigned int uint;

__device__ __nv_bfloat16 g_qWb[Bn * Qn * Dn];
__device__ __nv_bfloat16 g_qb[Bn * Qn * Dn];
__device__ __nv_bfloat16 g_Wt[Dn * Dn];       // W transposed: g_Wt[n*Dn+k] = W[k][n]

__device__ __forceinline__ uint packbf2(float lo, float hi) {
    uint r;
    asm("cvt.rn.bf16x2.f32 %0, %1, %2;" : "=r"(r) : "f"(hi), "f"(lo));
    return r;
}

// packed silu on bf16x2: x * sigmoid(x), sigmoid via tanh. 1 MUFU for 2 lanes.
__device__ __forceinline__ uint silu2(uint x) {
    const uint H = 0x3F003F00u;   // bf16x2 (0.5, 0.5)
    uint t;
    asm("mul.rn.bf16x2 %0, %1, %2;" : "=r"(t) : "r"(x), "r"(H));
    asm("tanh.approx.bf16x2 %0, %1;" : "=r"(t) : "r"(t));
    asm("fma.rn.bf16x2 %0, %1, %2, %3;" : "=r"(t) : "r"(t), "r"(H), "r"(H));
    uint r;
    asm("mul.rn.bf16x2 %0, %1, %2;" : "=r"(r) : "r"(x), "r"(t));
    return r;
}

#define HFMA2BF(d, a, b, c) \
    asm("fma.rn.bf16x2 %0, %1, %2, %3;" : "=r"(d) : "r"(a), "r"(b), "r"(c))

__device__ __forceinline__ void mma16816(float* c, uint a0, uint a1, uint a2, uint a3,
                                         uint b0, uint b1) {
    asm("mma.sync.aligned.m16n8k16.row.col.f32.bf16.bf16.f32 "
        "{%0,%1,%2,%3},{%4,%5,%6,%7},{%8,%9},{%0,%1,%2,%3};"
        : "+f"(c[0]), "+f"(c[1]), "+f"(c[2]), "+f"(c[3])
        : "r"(a0), "r"(a1), "r"(a2), "r"(a3), "r"(b0), "r"(b1));
}

__device__ __forceinline__ void mma16808(float& c0, float& c1, float& c2, float& c3,
                                         uint a0, uint a1, uint b0) {
    asm("mma.sync.aligned.m16n8k8.row.col.f32.bf16.bf16.f32 "
        "{%0,%1,%2,%3},{%4,%5},{%6},{%0,%1,%2,%3};"
        : "+f"(c0), "+f"(c1), "+f"(c2), "+f"(c3)
        : "r"(a0), "r"(a1), "r"(b0));
}

// ---------------------------------------------------------------------------
// Convert kernel: q -> bf16 (g_qb), W -> transposed bf16 (g_Wt).
// ---------------------------------------------------------------------------
__global__ __launch_bounds__(256) void convert_kernel(
    const float* __restrict__ q, const float* __restrict__ W)
{
    const int bid = blockIdx.x;
    const int tid = threadIdx.x;
    if (bid < 512) {
        // q: 1048576 floats = 524288 float2; 512 blocks x 256 thr x 4
        const float2* src = (const float2*)q;
        __nv_bfloat162* dst = (__nv_bfloat162*)g_qb;
#pragma unroll
        for (int r = 0; r < 4; r++) {
            int i = bid * 1024 + r * 256 + tid;
            float2 v = src[i];
            dst[i] = __floats2bfloat162_rn(v.x, v.y);
        }
    } else {
        // W transpose: 65536 elems; 64 blocks x 256 thr x 4
        int b2 = bid - 512;
#pragma unroll
        for (int r = 0; r < 4; r++) {
            int e = b2 * 1024 + r * 256 + tid;
            int n = e >> 8, k = e & 255;
            g_Wt[n * Dn + k] = __float2bfloat16(W[k * Dn + n]);
        }
    }
}

// ---------------------------------------------------------------------------
// qW GEMM via mma: g_qWb[m][n] = sum_k g_qb[m][k] * W[k][n] (= g_Wt[n][k]).
// 64x64 tile, 8 warps = 4 (m sub 16) x 2 (n sub 32).
// ---------------------------------------------------------------------------
__global__ __launch_bounds__(256) void qw_mma_kernel()
{
    __shared__ __align__(16) __nv_bfloat16 At[64 * PITCH];
    __shared__ __align__(16) __nv_bfloat16 Bt[64 * PITCH];

    const int tid  = threadIdx.x;
    const int warp = tid >> 5;
    const int lane = tid & 31;
    const int m    = lane & 3;
    const int g    = lane >> 2;
    const int wq   = warp & 3;
    const int wk   = warp >> 2;
    const int bm   = blockIdx.x * 64;
    const int bn   = blockIdx.y * 64;

    float bacc[4][4];
#pragma unroll
    for (int n = 0; n < 4; n++)
#pragma unroll
        for (int j = 0; j < 4; j++) bacc[n][j] = 0.f;

#pragma unroll 1
    for (int k0 = 0; k0 < Dn; k0 += 64) {
        __syncthreads();
#pragma unroll
        for (int rep = 0; rep < 2; rep++) {
            int idx = tid + rep * 256;
            int r = idx >> 3, c8 = (idx & 7) * 8;
            *(uint4*)&At[r * PITCH + c8] = *(const uint4*)&g_qb[(bm + r) * Dn + k0 + c8];
            *(uint4*)&Bt[r * PITCH + c8] = *(const uint4*)&g_Wt[(bn + r) * Dn + k0 + c8];
        }
        __syncthreads();
#pragma unroll
        for (int s2 = 0; s2 < 4; s2++) {
            const int acol = 16 * s2 + 2 * m;
            const int arow = 16 * wq + g;
            uint a0 = *(const uint*)&At[arow * PITCH + acol];
            uint a1 = *(const uint*)&At[(arow + 8) * PITCH + acol];
            uint a2 = *(const uint*)&At[arow * PITCH + acol + 8];
            uint a3 = *(const uint*)&At[(arow + 8) * PITCH + acol + 8];
#pragma unroll
            for (int n = 0; n < 4; n++) {
                const int brow = 32 * wk + 8 * n + g;
                uint b0 = *(const uint*)&Bt[brow * PITCH + acol];
                uint b1 = *(const uint*)&Bt[brow * PITCH + acol + 8];
                mma16816(bacc[n], a0, a1, a2, a3, b0, b1);
            }
        }
    }
#pragma unroll
    for (int n = 0; n < 4; n++) {
        int row = bm + 16 * wq + g;
        int col = bn + 32 * wk + 8 * n + 2 * m;
        *(__nv_bfloat162*)&g_qWb[row * Dn + col] =
            __floats2bfloat162_rn(bacc[n][0], bacc[n][1]);
        *(__nv_bfloat162*)&g_qWb[(row + 8) * Dn + col] =
            __floats2bfloat162_rn(bacc[n][2], bacc[n][3]);
    }
}

// ---------------------------------------------------------------------------
// Fused kernel: bilinear (mma) + geo MLP (mma + packed bf16x2 silu).
// ---------------------------------------------------------------------------
__global__ __launch_bounds__(256, 2) void edge_head_mma_kernel(
    const float* __restrict__ coords,
    const int*   __restrict__ amask,
    const float* __restrict__ w1,
    const float* __restrict__ b1,
    const float* __restrict__ w2,
    const float* __restrict__ b2,
    const float* __restrict__ w3,
    const float* __restrict__ b3,
    const float* __restrict__ bias,
    float* __restrict__ out)
{
    __shared__ __align__(16) __nv_bfloat16 qWt[TQ * PITCH];
    __shared__ __align__(16) __nv_bfloat16 qt[TK * PITCH];
    __shared__ float  bilS[TQ * BPITCH];
    __shared__ __align__(8) uint2  B2s[4 * 8 * 32];
    __shared__ __align__(8) float2 b1p[32], b2p[32];
    __shared__ uint   w3bp[32];                        // bf16x2 w3 pairs
    __shared__ float  cxq[TQ], cyq[TQ], cxk[TK], cyk[TK];
    __shared__ int    aqs[TQ], aks[TK];
    __shared__ float  cadd;

    const int tid  = threadIdx.x;
    const int warp = tid >> 5;
    const int lane = tid & 31;
    const int m    = lane & 3;
    const int g    = lane >> 2;
    const int wq   = warp & 3;
    const int wk   = warp >> 2;
    const int b    = blockIdx.z;
    const int q0   = blockIdx.y * TQ;
    const int k0   = blockIdx.x * TK;

    if (tid < GH) {
        int i = tid;
        int gq = b * Qn + q0 + i;
        cxq[i] = coords[gq * 2 + 0]; cyq[i] = coords[gq * 2 + 1];
        aqs[i] = amask[gq];
    } else if (tid < 2 * GH) {
        int i = tid - GH;
        int gk = b * Qn + k0 + i;
        cxk[i] = coords[gk * 2 + 0]; cyk[i] = coords[gk * 2 + 1];
        aks[i] = amask[gk];
    }
    if (tid == 0) cadd = b3[0] + bias[0];

#pragma unroll
    for (int e = tid; e < 1024; e += 256) {
        int s  = e >> 8;
        int n  = (e >> 5) & 7;
        int ln = e & 31;
        int em = ln & 3, eg = ln >> 2;
        int kk = 16 * s + 2 * em;
        int nn = 8 * n + eg;
        uint2 v;
        v.x = packbf2(w2[kk * GH + nn],       w2[(kk + 1) * GH + nn]);
        v.y = packbf2(w2[(kk + 8) * GH + nn], w2[(kk + 9) * GH + nn]);
        B2s[e] = v;
    }
    if (tid < 32) {
        int nb = tid >> 2, mm = tid & 3;
        int c = 8 * nb + 2 * mm;
        b1p[tid]  = make_float2(b1[c], b1[c + 1]);
        b2p[tid]  = make_float2(b2[c], b2[c + 1]);
        w3bp[tid] = packbf2(w3[c], w3[c + 1]);
    }

    uint W1B[8];
#pragma unroll
    for (int nb = 0; nb < 8; nb++) {
        int nn = 8 * nb + g;
        W1B[nb] = (m < 3) ? packbf2(w1[(2 * m) * GH + nn], w1[(2 * m + 1) * GH + nn]) : 0u;
    }

    // ---- bilinear via mma ----
    float bacc[4][4];
#pragma unroll
    for (int n = 0; n < 4; n++)
#pragma unroll
        for (int j = 0; j < 4; j++) bacc[n][j] = 0.f;

#pragma unroll 1
    for (int d0 = 0; d0 < Dn; d0 += 64) {
        __syncthreads();
#pragma unroll
        for (int rep = 0; rep < 2; rep++) {
            int idx = tid + rep * 256;
            int r = idx >> 3, c8 = (idx & 7) * 8;
            *(uint4*)&qWt[r * PITCH + c8] =
                *(const uint4*)&g_qWb[(b * Qn + q0 + r) * Dn + d0 + c8];
            *(uint4*)&qt[r * PITCH + c8] =
                *(const uint4*)&g_qb[(b * Qn + k0 + r) * Dn + d0 + c8];
        }
        __syncthreads();
#pragma unroll
        for (int s2 = 0; s2 < 4; s2++) {
            const int acol = 16 * s2 + 2 * m;
            const int arow = 16 * wq + g;
            uint a0 = *(const uint*)&qWt[arow * PITCH + acol];
            uint a1 = *(const uint*)&qWt[(arow + 8) * PITCH + acol];
            uint a2 = *(const uint*)&qWt[arow * PITCH + acol + 8];
            uint a3 = *(const uint*)&qWt[(arow + 8) * PITCH + acol + 8];
#pragma unroll
            for (int n = 0; n < 4; n++) {
                const int brow = 32 * wk + 8 * n + g;
                uint b0 = *(const uint*)&qt[brow * PITCH + acol];
                uint b1v = *(const uint*)&qt[brow * PITCH + acol + 8];
                mma16816(bacc[n], a0, a1, a2, a3, b0, b1v);
            }
        }
    }
    __syncthreads();
#pragma unroll
    for (int n = 0; n < 4; n++) {
        int row = 16 * wq + g;
        int col = 32 * wk + 8 * n + 2 * m;
        *(float2*)&bilS[row * BPITCH + col]       = make_float2(bacc[n][0], bacc[n][1]);
        *(float2*)&bilS[(row + 8) * BPITCH + col] = make_float2(bacc[n][2], bacc[n][3]);
    }
    __syncthreads();

    // ---- MLP phase ----
    const int row0 = 16 * wq + g;
    const int row1 = row0 + 8;
    const float qx0 = cxq[row0], qy0 = cyq[row0];
    const float qx1 = cxq[row1], qy1 = cyq[row1];
    const bool  qa0 = (aqs[row0] != 0), qa1 = (aqs[row1] != 0);
    const float caddv = cadd;

#pragma unroll 1
    for (int kc = 0; kc < 32; kc++) {
        const int k  = 32 * wk + kc;
        const int gk = k0 + k;

        if (aks[k] == 0) {
            if (m == 0) {
                out[((long)(b * Qn + q0 + row0)) * Qn + gk] = -1e9f;
                out[((long)(b * Qn + q0 + row1)) * Qn + gk] = -1e9f;
            }
            continue;
        }

        const float kx = cxk[k], ky = cyk[k];
        float dx0 = qx0 - kx, dy0 = qy0 - ky;
        float dx1 = qx1 - kx, dy1 = qy1 - ky;
        float d20 = fmaf(dx0, dx0, dy0 * dy0);
        float d21 = fmaf(dx1, dx1, dy1 * dy1);
        float ds0 = sqrtf(d20 + 1e-8f);
        float ds1 = sqrtf(d21 + 1e-8f);
        bool mz0 = (fabsf(dx0) < 1e-6f) && (fabsf(dy0) < 1e-6f);
        bool mz1 = (fabsf(dx1) < 1e-6f) && (fabsf(dy1) < 1e-6f);
        float xs0 = mz0 ? 1e-6f : dx0, ys0 = mz0 ? 1e-6f : dy0;
        float xs1 = mz1 ? 1e-6f : dx1, ys1 = mz1 ? 1e-6f : dy1;
        float rh0 = rsqrtf(fmaf(xs0, xs0, ys0 * ys0));
        float rh1 = rsqrtf(fmaf(xs1, xs1, ys1 * ys1));
        float sa0 = ys0 * rh0, ca0 = xs0 * rh0;
        float sa1 = ys1 * rh1, ca1 = xs1 * rh1;

        float flo0, fhi0, flo1, fhi1;
        if (m == 0)      { flo0 = dx0; fhi0 = dy0; flo1 = dx1; fhi1 = dy1; }
        else if (m == 1) { flo0 = ds0; fhi0 = d20; flo1 = ds1; fhi1 = d21; }
        else if (m == 2) { flo0 = sa0; fhi0 = ca0; flo1 = sa1; fhi1 = ca1; }
        else             { flo0 = 0.f; fhi0 = 0.f; flo1 = 0.f; fhi1 = 0.f; }
        const uint GA0 = packbf2(flo0, fhi0);
        const uint GA1 = packbf2(flo1, fhi1);

        float acc2[8][4];
#pragma unroll
        for (int n = 0; n < 8; n++) {
            float2 bv = b2p[n * 4 + m];
            acc2[n][0] = bv.x; acc2[n][1] = bv.y;
            acc2[n][2] = bv.x; acc2[n][3] = bv.y;
        }

#pragma unroll
        for (int s = 0; s < 4; s++) {
            uint a0, a1, a2, a3;
            {
                int nb = 2 * s;
                float2 bv = b1p[nb * 4 + m];
                float c0 = bv.x, c1 = bv.y, c2 = bv.x, c3 = bv.y;
                mma16808(c0, c1, c2, c3, GA0, GA1, W1B[nb]);
                a0 = silu2(packbf2(c0, c1));
                a1 = silu2(packbf2(c2, c3));
            }
            {
                int nb = 2 * s + 1;
                float2 bv = b1p[nb * 4 + m];
                float c0 = bv.x, c1 = bv.y, c2 = bv.x, c3 = bv.y;
                mma16808(c0, c1, c2, c3, GA0, GA1, W1B[nb]);
                a2 = silu2(packbf2(c0, c1));
                a3 = silu2(packbf2(c2, c3));
            }
            const uint2* Brow = &B2s[(s * 8) * 32 + lane];
#pragma unroll
            for (int n = 0; n < 8; n++) {
                uint2 Bv = Brow[n * 32];
                mma16816(acc2[n], a0, a1, a2, a3, Bv.x, Bv.y);
            }
        }

        // epilogue: packed silu(h2) . w3, bf16x2 accumulate
        uint P0 = 0u, P1 = 0u;
#pragma unroll
        for (int n = 0; n < 8; n++) {
            uint wv = w3bp[n * 4 + m];
            uint s01 = silu2(packbf2(acc2[n][0], acc2[n][1]));
            uint s23 = silu2(packbf2(acc2[n][2], acc2[n][3]));
            HFMA2BF(P0, s01, wv, P0);
            HFMA2BF(P1, s23, wv, P1);
        }
        float p0 = __uint_as_float(P0 << 16) + __uint_as_float(P0 & 0xffff0000u);
        float p1 = __uint_as_float(P1 << 16) + __uint_as_float(P1 & 0xffff0000u);
        p0 += __shfl_xor_sync(0xffffffffu, p0, 1);
        p0 += __shfl_xor_sync(0xffffffffu, p0, 2);
        p1 += __shfl_xor_sync(0xffffffffu, p1, 1);
        p1 += __shfl_xor_sync(0xffffffffu, p1, 2);

        if (m == 0) {
            const int qi0 = q0 + row0, qi1 = q0 + row1;
            float v0 = qa0 ? ((qi0 == gk) ? 0.f
                              : p0 + bilS[row0 * BPITCH + k] + caddv) : -1e9f;
            float v1 = qa1 ? ((qi1 == gk) ? 0.f
                              : p1 + bilS[row1 * BPITCH + k] + caddv) : -1e9f;
            out[((long)(b * Qn + qi0)) * Qn + gk] = v0;
            out[((long)(b * Qn + qi1)) * Qn + gk] = v1;
        }
    }
}

// ---------------------------------------------------------------------------
extern "C" void kernel_launch(void* const* d_in, const int* in_sizes, int n_in,
                              void* d_out, int out_size)
{
    const float* q      = (const float*)d_in[0];
    const float* coords = (const float*)d_in[1];
    const int*   amask  = (const int*)d_in[2];
    const float* W      = (const float*)d_in[3];
    const float* w1     = (const float*)d_in[4];
    const float* b1     = (const float*)d_in[5];
    const float* w2     = (const float*)d_in[6];
    const float* b2     = (const float*)d_in[7];
    const float* w3     = (const float*)d_in[8];
    const float* b3     = (const float*)d_in[9];
    const float* bias   = (const float*)d_in[10];
    float* out = (float*)d_out;

    convert_kernel<<<576, 256>>>(q, W);
    {
        dim3 grid((Bn * Qn) / 64, Dn / 64);
        qw_mma_kernel<<<grid, 256>>>();
    }
    {
        dim3 grid(Qn / TK, Qn / TQ, Bn);
        edge_head_mma_kernel<<<grid, 256>>>(coords, amask,
                                            w1, b1, w2, b2, w3, b3, bias, out);
    }
}

// round 10
// speedup vs baseline: 8.1054x; 1.0473x over previous
#include <cuda_runtime.h>
#include <cuda_bf16.h>
#include <math.h>

#define Bn 4
#define Qn 1024
#define Dn 256
#define GH 64
#define TQ 64
#define TK 64
#define PITCH 72    // bf16 pitch for mma smem tiles
#define BPITCH 66   // fp32 pitch for bil staging

typedef unsigned int uint;

__device__ __nv_bfloat16 g_qWb[Bn * Qn * Dn];
__device__ __nv_bfloat16 g_qb[Bn * Qn * Dn];
__device__ __nv_bfloat16 g_Wt[Dn * Dn];       // W transposed: g_Wt[n*Dn+k] = W[k][n]

__device__ __forceinline__ uint packbf2(float lo, float hi) {
    uint r;
    asm("cvt.rn.bf16x2.f32 %0, %1, %2;" : "=r"(r) : "f"(hi), "f"(lo));
    return r;
}

// packed silu on bf16x2: x * sigmoid(x); 1 MUFU for 2 lanes.
__device__ __forceinline__ uint silu2(uint x) {
    const uint H = 0x3F003F00u;   // bf16x2 (0.5, 0.5)
    uint t;
    asm("mul.rn.bf16x2 %0, %1, %2;" : "=r"(t) : "r"(x), "r"(H));
    asm("tanh.approx.bf16x2 %0, %1;" : "=r"(t) : "r"(t));
    asm("fma.rn.bf16x2 %0, %1, %2, %3;" : "=r"(t) : "r"(t), "r"(H), "r"(H));
    uint r;
    asm("mul.rn.bf16x2 %0, %1, %2;" : "=r"(r) : "r"(x), "r"(t));
    return r;
}

#define HFMA2BF(d, a, b, c) \
    asm("fma.rn.bf16x2 %0, %1, %2, %3;" : "=r"(d) : "r"(a), "r"(b), "r"(c))

__device__ __forceinline__ void mma16816(float* c, uint a0, uint a1, uint a2, uint a3,
                                         uint b0, uint b1) {
    asm("mma.sync.aligned.m16n8k16.row.col.f32.bf16.bf16.f32 "
        "{%0,%1,%2,%3},{%4,%5,%6,%7},{%8,%9},{%0,%1,%2,%3};"
        : "+f"(c[0]), "+f"(c[1]), "+f"(c[2]), "+f"(c[3])
        : "r"(a0), "r"(a1), "r"(a2), "r"(a3), "r"(b0), "r"(b1));
}

__device__ __forceinline__ void mma16808(float& c0, float& c1, float& c2, float& c3,
                                         uint a0, uint a1, uint b0) {
    asm("mma.sync.aligned.m16n8k8.row.col.f32.bf16.bf16.f32 "
        "{%0,%1,%2,%3},{%4,%5},{%6},{%0,%1,%2,%3};"
        : "+f"(c0), "+f"(c1), "+f"(c2), "+f"(c3)
        : "r"(a0), "r"(a1), "r"(b0));
}

// ---------------------------------------------------------------------------
// Convert kernel: q -> bf16 (float4-wide), W -> transposed bf16.
// ---------------------------------------------------------------------------
__global__ __launch_bounds__(256) void convert_kernel(
    const float* __restrict__ q, const float* __restrict__ W)
{
    const int bid = blockIdx.x;
    const int tid = threadIdx.x;
    if (bid < 1024) {
        // q: 1048576 floats = 262144 float4; one float4 per thread
        int i = bid * 256 + tid;
        float4 v = ((const float4*)q)[i];
        uint2 o;
        o.x = packbf2(v.x, v.y);
        o.y = packbf2(v.z, v.w);
        ((uint2*)g_qb)[i] = o;
    } else {
        // W transpose: 65536 elems; 64 blocks x 256 thr x 4 (coalesced reads)
        int b2 = bid - 1024;
#pragma unroll
        for (int r = 0; r < 4; r++) {
            int e = b2 * 1024 + r * 256 + tid;
            int k = e >> 8, n = e & 255;
            g_Wt[n * Dn + k] = __float2bfloat16(W[k * Dn + n]);
        }
    }
}

// ---------------------------------------------------------------------------
// qW GEMM via mma: g_qWb = g_qb @ W.
// ---------------------------------------------------------------------------
__global__ __launch_bounds__(256) void qw_mma_kernel()
{
    __shared__ __align__(16) __nv_bfloat16 At[64 * PITCH];
    __shared__ __align__(16) __nv_bfloat16 Bt[64 * PITCH];

    const int tid  = threadIdx.x;
    const int warp = tid >> 5;
    const int lane = tid & 31;
    const int m    = lane & 3;
    const int g    = lane >> 2;
    const int wq   = warp & 3;
    const int wk   = warp >> 2;
    const int bm   = blockIdx.x * 64;
    const int bn   = blockIdx.y * 64;

    float bacc[4][4];
#pragma unroll
    for (int n = 0; n < 4; n++)
#pragma unroll
        for (int j = 0; j < 4; j++) bacc[n][j] = 0.f;

#pragma unroll 1
    for (int k0 = 0; k0 < Dn; k0 += 64) {
        __syncthreads();
#pragma unroll
        for (int rep = 0; rep < 2; rep++) {
            int idx = tid + rep * 256;
            int r = idx >> 3, c8 = (idx & 7) * 8;
            *(uint4*)&At[r * PITCH + c8] = *(const uint4*)&g_qb[(bm + r) * Dn + k0 + c8];
            *(uint4*)&Bt[r * PITCH + c8] = *(const uint4*)&g_Wt[(bn + r) * Dn + k0 + c8];
        }
        __syncthreads();
#pragma unroll
        for (int s2 = 0; s2 < 4; s2++) {
            const int acol = 16 * s2 + 2 * m;
            const int arow = 16 * wq + g;
            uint a0 = *(const uint*)&At[arow * PITCH + acol];
            uint a1 = *(const uint*)&At[(arow + 8) * PITCH + acol];
            uint a2 = *(const uint*)&At[arow * PITCH + acol + 8];
            uint a3 = *(const uint*)&At[(arow + 8) * PITCH + acol + 8];
#pragma unroll
            for (int n = 0; n < 4; n++) {
                const int brow = 32 * wk + 8 * n + g;
                uint b0 = *(const uint*)&Bt[brow * PITCH + acol];
                uint b1 = *(const uint*)&Bt[brow * PITCH + acol + 8];
                mma16816(bacc[n], a0, a1, a2, a3, b0, b1);
            }
        }
    }
#pragma unroll
    for (int n = 0; n < 4; n++) {
        int row = bm + 16 * wq + g;
        int col = bn + 32 * wk + 8 * n + 2 * m;
        *(__nv_bfloat162*)&g_qWb[row * Dn + col] =
            __floats2bfloat162_rn(bacc[n][0], bacc[n][1]);
        *(__nv_bfloat162*)&g_qWb[(row + 8) * Dn + col] =
            __floats2bfloat162_rn(bacc[n][2], bacc[n][3]);
    }
}

// ---------------------------------------------------------------------------
// Fused kernel: bilinear (mma) + geo MLP (mma + shared GA feature table).
// ---------------------------------------------------------------------------
__global__ __launch_bounds__(256, 2) void edge_head_mma_kernel(
    const float* __restrict__ coords,
    const int*   __restrict__ amask,
    const float* __restrict__ w1,
    const float* __restrict__ b1,
    const float* __restrict__ w2,
    const float* __restrict__ b2,
    const float* __restrict__ w3,
    const float* __restrict__ b3,
    const float* __restrict__ bias,
    float* __restrict__ out)
{
    // union region: bilinear tiles (18432B) / GA feature table (16384B)
    __shared__ __align__(16) char uraw[TQ * PITCH * 2 + TK * PITCH * 2];
    __shared__ float  bilS[TQ * BPITCH];
    __shared__ __align__(16) uint4 B4s[4 * 4 * 32];   // layer-2 B frag pairs, 8KB
    __shared__ __align__(8) float2 b1p[32], b2p[32];
    __shared__ uint   w3bp[32];
    __shared__ float  cxq[TQ], cyq[TQ], cxk[TK], cyk[TK];
    __shared__ int    aqs[TQ], aks[TK];
    __shared__ float  cadd;

    __nv_bfloat16* qWt = (__nv_bfloat16*)uraw;
    __nv_bfloat16* qt  = (__nv_bfloat16*)(uraw + TQ * PITCH * 2);
    uint*          GAs = (uint*)uraw;     // [16 k][64 row][4] bf16x2 feature pairs

    const int tid  = threadIdx.x;
    const int warp = tid >> 5;
    const int lane = tid & 31;
    const int m    = lane & 3;
    const int g    = lane >> 2;
    const int wq   = warp & 3;
    const int wk   = warp >> 2;
    const int b    = blockIdx.z;
    const int q0   = blockIdx.y * TQ;
    const int k0   = blockIdx.x * TK;

    if (tid < GH) {
        int i = tid;
        int gq = b * Qn + q0 + i;
        cxq[i] = coords[gq * 2 + 0]; cyq[i] = coords[gq * 2 + 1];
        aqs[i] = amask[gq];
    } else if (tid < 2 * GH) {
        int i = tid - GH;
        int gk = b * Qn + k0 + i;
        cxk[i] = coords[gk * 2 + 0]; cyk[i] = coords[gk * 2 + 1];
        aks[i] = amask[gk];
    }
    if (tid == 0) cadd = b3[0] + bias[0];

    // layer-2 B fragment pairs: entry (s, np, lane) -> frags n=2np, 2np+1
#pragma unroll
    for (int e = tid; e < 512; e += 256) {
        int s  = e >> 7;
        int np = (e >> 5) & 3;
        int ln = e & 31;
        int em = ln & 3, eg = ln >> 2;
        int kk = 16 * s + 2 * em;
        uint4 v;
        int n0 = 8 * (2 * np) + eg;
        v.x = packbf2(w2[kk * GH + n0],       w2[(kk + 1) * GH + n0]);
        v.y = packbf2(w2[(kk + 8) * GH + n0], w2[(kk + 9) * GH + n0]);
        int n1 = 8 * (2 * np + 1) + eg;
        v.z = packbf2(w2[kk * GH + n1],       w2[(kk + 1) * GH + n1]);
        v.w = packbf2(w2[(kk + 8) * GH + n1], w2[(kk + 9) * GH + n1]);
        B4s[e] = v;
    }
    if (tid < 32) {
        int nb = tid >> 2, mm = tid & 3;
        int c = 8 * nb + 2 * mm;
        b1p[tid]  = make_float2(b1[c], b1[c + 1]);
        b2p[tid]  = make_float2(b2[c], b2[c + 1]);
        w3bp[tid] = packbf2(w3[c], w3[c + 1]);
    }

    uint W1B[8];
#pragma unroll
    for (int nb = 0; nb < 8; nb++) {
        int nn = 8 * nb + g;
        W1B[nb] = (m < 3) ? packbf2(w1[(2 * m) * GH + nn], w1[(2 * m + 1) * GH + nn]) : 0u;
    }

    // ---- bilinear via mma ----
    float bacc[4][4];
#pragma unroll
    for (int n = 0; n < 4; n++)
#pragma unroll
        for (int j = 0; j < 4; j++) bacc[n][j] = 0.f;

#pragma unroll 1
    for (int d0 = 0; d0 < Dn; d0 += 64) {
        __syncthreads();
#pragma unroll
        for (int rep = 0; rep < 2; rep++) {
            int idx = tid + rep * 256;
            int r = idx >> 3, c8 = (idx & 7) * 8;
            *(uint4*)&qWt[r * PITCH + c8] =
                *(const uint4*)&g_qWb[(b * Qn + q0 + r) * Dn + d0 + c8];
            *(uint4*)&qt[r * PITCH + c8] =
                *(const uint4*)&g_qb[(b * Qn + k0 + r) * Dn + d0 + c8];
        }
        __syncthreads();
#pragma unroll
        for (int s2 = 0; s2 < 4; s2++) {
            const int acol = 16 * s2 + 2 * m;
            const int arow = 16 * wq + g;
            uint a0 = *(const uint*)&qWt[arow * PITCH + acol];
            uint a1 = *(const uint*)&qWt[(arow + 8) * PITCH + acol];
            uint a2 = *(const uint*)&qWt[arow * PITCH + acol + 8];
            uint a3 = *(const uint*)&qWt[(arow + 8) * PITCH + acol + 8];
#pragma unroll
            for (int n = 0; n < 4; n++) {
                const int brow = 32 * wk + 8 * n + g;
                uint b0 = *(const uint*)&qt[brow * PITCH + acol];
                uint b1v = *(const uint*)&qt[brow * PITCH + acol + 8];
                mma16816(bacc[n], a0, a1, a2, a3, b0, b1v);
            }
        }
    }
    __syncthreads();
#pragma unroll
    for (int n = 0; n < 4; n++) {
        int row = 16 * wq + g;
        int col = 32 * wk + 8 * n + 2 * m;
        *(float2*)&bilS[row * BPITCH + col]       = make_float2(bacc[n][0], bacc[n][1]);
        *(float2*)&bilS[(row + 8) * BPITCH + col] = make_float2(bacc[n][2], bacc[n][3]);
    }

    // ---- MLP phase: 4 passes of 16 k's; GA table overlays bilinear tiles ----
    const int row0 = 16 * wq + g;
    const int row1 = row0 + 8;
    const bool qa0 = (aqs[row0] != 0), qa1 = (aqs[row1] != 0);
    const float caddv = cadd;

#pragma unroll 1
    for (int p = 0; p < 4; p++) {
        __syncthreads();   // prior GA/tile reads done before overwrite
        // precompute GA features for k in [16p, 16p+16), all 64 rows
#pragma unroll
        for (int r = 0; r < 4; r++) {
            int e   = tid + 256 * r;        // 0..1023
            int kl  = e >> 6;               // 0..15
            int row = e & 63;
            int k   = 16 * p + kl;
            if (aks[k] != 0) {
                float dxv = cxq[row] - cxk[k];
                float dyv = cyq[row] - cyk[k];
                float d2v = fmaf(dxv, dxv, dyv * dyv);
                float dsv = sqrtf(d2v + 1e-8f);
                bool  mzv = (fabsf(dxv) < 1e-6f) && (fabsf(dyv) < 1e-6f);
                float xsv = mzv ? 1e-6f : dxv;
                float ysv = mzv ? 1e-6f : dyv;
                float rhv = rsqrtf(fmaf(xsv, xsv, ysv * ysv));
                uint4 gv;
                gv.x = packbf2(dxv, dyv);
                gv.y = packbf2(dsv, d2v);
                gv.z = packbf2(ysv * rhv, xsv * rhv);
                gv.w = 0u;
                *(uint4*)&GAs[(kl * 64 + row) * 4] = gv;
            }
        }
        __syncthreads();

#pragma unroll 1
        for (int i = 0; i < 8; i++) {
            const int kl = 8 * wk + i;
            const int k  = 16 * p + kl;
            const int gk = k0 + k;
            const int mw = i >> 1;          // writer lane in m-group

            if (aks[k] == 0) {
                if (m == mw) {
                    out[((long)(b * Qn + q0 + row0)) * Qn + gk] = -1e9f;
                    out[((long)(b * Qn + q0 + row1)) * Qn + gk] = -1e9f;
                }
                continue;
            }

            const uint GA0 = GAs[(kl * 64 + row0) * 4 + m];
            const uint GA1 = GAs[(kl * 64 + row1) * 4 + m];

            float acc2[8][4];
#pragma unroll
            for (int n = 0; n < 8; n++) {
                float2 bv = b2p[n * 4 + m];
                acc2[n][0] = bv.x; acc2[n][1] = bv.y;
                acc2[n][2] = bv.x; acc2[n][3] = bv.y;
            }

#pragma unroll
            for (int s = 0; s < 4; s++) {
                uint a0, a1, a2, a3;
                {
                    int nb = 2 * s;
                    float2 bv = b1p[nb * 4 + m];
                    float c0 = bv.x, c1 = bv.y, c2 = bv.x, c3 = bv.y;
                    mma16808(c0, c1, c2, c3, GA0, GA1, W1B[nb]);
                    a0 = silu2(packbf2(c0, c1));
                    a1 = silu2(packbf2(c2, c3));
                }
                {
                    int nb = 2 * s + 1;
                    float2 bv = b1p[nb * 4 + m];
                    float c0 = bv.x, c1 = bv.y, c2 = bv.x, c3 = bv.y;
                    mma16808(c0, c1, c2, c3, GA0, GA1, W1B[nb]);
                    a2 = silu2(packbf2(c0, c1));
                    a3 = silu2(packbf2(c2, c3));
                }
                const uint4* Brow = &B4s[(s * 4) * 32 + lane];
#pragma unroll
                for (int np = 0; np < 4; np++) {
                    uint4 Bv = Brow[np * 32];
                    mma16816(acc2[2 * np],     a0, a1, a2, a3, Bv.x, Bv.y);
                    mma16816(acc2[2 * np + 1], a0, a1, a2, a3, Bv.z, Bv.w);
                }
            }

            // epilogue: packed silu(h2) . w3
            uint P0 = 0u, P1 = 0u;
#pragma unroll
            for (int n = 0; n < 8; n++) {
                uint wv = w3bp[n * 4 + m];
                uint s01 = silu2(packbf2(acc2[n][0], acc2[n][1]));
                uint s23 = silu2(packbf2(acc2[n][2], acc2[n][3]));
                HFMA2BF(P0, s01, wv, P0);
                HFMA2BF(P1, s23, wv, P1);
            }
            float p0 = __uint_as_float(P0 << 16) + __uint_as_float(P0 & 0xffff0000u);
            float p1 = __uint_as_float(P1 << 16) + __uint_as_float(P1 & 0xffff0000u);
            p0 += __shfl_xor_sync(0xffffffffu, p0, 1);
            p0 += __shfl_xor_sync(0xffffffffu, p0, 2);
            p1 += __shfl_xor_sync(0xffffffffu, p1, 1);
            p1 += __shfl_xor_sync(0xffffffffu, p1, 2);

            if (m == mw) {
                const int qi0 = q0 + row0, qi1 = q0 + row1;
                float v0 = qa0 ? ((qi0 == gk) ? 0.f
                                  : p0 + bilS[row0 * BPITCH + k] + caddv) : -1e9f;
                float v1 = qa1 ? ((qi1 == gk) ? 0.f
                                  : p1 + bilS[row1 * BPITCH + k] + caddv) : -1e9f;
                out[((long)(b * Qn + qi0)) * Qn + gk] = v0;
                out[((long)(b * Qn + qi1)) * Qn + gk] = v1;
            }
        }
    }
}

// ---------------------------------------------------------------------------
extern "C" void kernel_launch(void* const* d_in, const int* in_sizes, int n_in,
                              void* d_out, int out_size)
{
    const float* q      = (const float*)d_in[0];
    const float* coords = (const float*)d_in[1];
    const int*   amask  = (const int*)d_in[2];
    const float* W      = (const float*)d_in[3];
    const float* w1     = (const float*)d_in[4];
    const float* b1     = (const float*)d_in[5];
    const float* w2     = (const float*)d_in[6];
    const float* b2     = (const float*)d_in[7];
    const float* w3     = (const float*)d_in[8];
    const float* b3     = (const float*)d_in[9];
    const float* bias   = (const float*)d_in[10];
    float* out = (float*)d_out;

    convert_kernel<<<1088, 256>>>(q, W);
    {
        dim3 grid((Bn * Qn) / 64, Dn / 64);
        qw_mma_kernel<<<grid, 256>>>();
    }
    {
        dim3 grid(Qn / TK, Qn / TQ, Bn);
        edge_head_mma_kernel<<<grid, 256>>>(coords, amask,
                                            w1, b1, w2, b2, w3, b3, bias, out);
    }
}